// round 1
// baseline (speedup 1.0000x reference)
#include <cuda_runtime.h>
#include <cuda_bf16.h>
#include <math.h>

// Problem constants
#define K_ 128
#define J_ 4
#define N_ 64
#define R_ 32
#define T_ 32
#define S_ 256
#define A_ 4
#define D_ 64
#define Z_ (K_*J_)   // 512
#define TM1 (T_-1)   // 31 nodes after merge
#define RP1 (R_+1)   // 33

// Output segment offsets (floats), concatenated reference tuple order
// merge1[K,33], merge2[K,33], b1[K,33], b2[K,33], embr[K,33,64],
// lc[K,31], h[K,31], embt[K,31,64], lf[K,31,256,4], log_pi_new[K], log_weight[K], log_lik[K]
#define O0 0u
#define O1 4224u
#define O2 8448u
#define O3 12672u
#define O4 16896u
#define O5 287232u
#define O6 291200u
#define O7 295168u
#define O8 549120u
#define O9 4612352u
#define O10 4612480u
#define O11 4612608u

#define LOG10F 2.302585092994045684f

// ---------------- scratch (device globals; no allocation) ----------------
__device__ float g_ckept[K_*T_];
__device__ float g_ctotal[K_];
__device__ float g_sumb1[K_];
__device__ float g_sumb2[K_];
__device__ float g_flc[K_];
__device__ int   g_cnt[K_];
__device__ float g_logw[Z_];
__device__ float g_lpn[Z_];
__device__ float g_llik[Z_];
__device__ float g_P1[Z_*16];
__device__ float g_P2[Z_*16];
__device__ int   g_sel[K_];

// ---------------- helpers ----------------
__device__ __forceinline__ float f_logdf(const float* logdf, int l) {
    int di = 2*l - 3;
    di = max(0, min(2*N_ - 1, di));
    return logdf[di];
}

// 4x4 matrix exponential: scaling-and-squaring + Taylor order 12.
__device__ void expm4(const float* M, float* E) {
    float nrm = 0.f;
    #pragma unroll
    for (int r = 0; r < 4; r++) {
        float rs = fabsf(M[r*4+0]) + fabsf(M[r*4+1]) + fabsf(M[r*4+2]) + fabsf(M[r*4+3]);
        nrm = fmaxf(nrm, rs);
    }
    int s = 0;
    while (nrm > 0.5f && s < 40) { nrm *= 0.5f; s++; }
    float sc = ldexpf(1.0f, -s);
    float A[16], Tm[16];
    #pragma unroll
    for (int i = 0; i < 16; i++) { A[i] = M[i] * sc; Tm[i] = A[i]; E[i] = A[i]; }
    E[0] += 1.f; E[5] += 1.f; E[10] += 1.f; E[15] += 1.f;
    for (int n = 2; n <= 12; n++) {
        float Tn[16];
        float invn = 1.0f / (float)n;
        #pragma unroll
        for (int r = 0; r < 4; r++)
            #pragma unroll
            for (int c = 0; c < 4; c++) {
                float sum = Tm[r*4+0]*A[0*4+c] + Tm[r*4+1]*A[1*4+c]
                          + Tm[r*4+2]*A[2*4+c] + Tm[r*4+3]*A[3*4+c];
                Tn[r*4+c] = sum * invn;
            }
        #pragma unroll
        for (int i = 0; i < 16; i++) { Tm[i] = Tn[i]; E[i] += Tn[i]; }
    }
    for (int q = 0; q < s; q++) {
        float Sq[16];
        #pragma unroll
        for (int r = 0; r < 4; r++)
            #pragma unroll
            for (int c = 0; c < 4; c++)
                Sq[r*4+c] = E[r*4+0]*E[0*4+c] + E[r*4+1]*E[1*4+c]
                          + E[r*4+2]*E[2*4+c] + E[r*4+3]*E[3*4+c];
        #pragma unroll
        for (int i = 0; i < 16; i++) E[i] = Sq[i];
    }
}

// ---------------- Kernel A: per-particle kept-node constants ----------------
// grid = K, block = 256
__global__ void kA(const int* __restrict__ indexes,
                   const float* __restrict__ b1r, const float* __restrict__ b2r,
                   const int* __restrict__ lc, const float* __restrict__ embt,
                   const float* __restrict__ lf, const float* __restrict__ Wstat,
                   const float* __restrict__ logdf) {
    int k = blockIdx.x;
    int gk = indexes[k];
    int tid = threadIdx.x;
    __shared__ float s_logit[T_][A_];
    __shared__ float s_p[T_][A_];
    __shared__ float s_part[T_][8];
    __shared__ float s_c[T_];

    if (tid < T_*A_) {  // 128 threads: one (t,a) dot each
        int t = tid >> 2, a = tid & 3;
        const float* e = embt + (size_t)(gk*T_ + t)*D_;
        float sum = 0.f;
        #pragma unroll 8
        for (int d = 0; d < D_; d++) sum += e[d] * Wstat[d*A_ + a];
        s_logit[t][a] = sum;
    }
    __syncthreads();
    if (tid < T_) {
        float l0 = s_logit[tid][0], l1 = s_logit[tid][1], l2 = s_logit[tid][2], l3 = s_logit[tid][3];
        float m = fmaxf(fmaxf(l0,l1), fmaxf(l2,l3));
        float e0 = __expf(l0-m), e1 = __expf(l1-m), e2 = __expf(l2-m), e3 = __expf(l3-m);
        float inv = 1.f/(e0+e1+e2+e3);
        s_p[tid][0]=e0*inv; s_p[tid][1]=e1*inv; s_p[tid][2]=e2*inv; s_p[tid][3]=e3*inv;
    }
    __syncthreads();

    // c_kept[t] = sum_s log( dot(exp(lf[t,s,:]), p[t,:]) )
    {
        int t = tid >> 3, lane = tid & 7;
        float p0 = s_p[t][0], p1 = s_p[t][1], p2 = s_p[t][2], p3 = s_p[t][3];
        const float4* row = (const float4*)(lf + (size_t)(gk*T_ + t)*S_*A_);
        float acc = 0.f;
        #pragma unroll 4
        for (int i = 0; i < S_/8; i++) {
            float4 v = row[lane + 8*i];
            float dot = p0*__expf(v.x) + p1*__expf(v.y) + p2*__expf(v.z) + p3*__expf(v.w);
            acc += __logf(dot);
        }
        s_part[t][lane] = acc;
    }
    __syncthreads();
    if (tid < T_) {
        float c = 0.f;
        #pragma unroll
        for (int i = 0; i < 8; i++) c += s_part[tid][i];
        g_ckept[k*T_ + tid] = c;
        s_c[tid] = c;
    }
    __syncthreads();
    if (tid == 0) {
        float tot = 0.f;
        for (int i = 0; i < T_; i++) tot += s_c[i];
        g_ctotal[k] = tot;
        float sb1 = 0.f, sb2 = 0.f;
        for (int r = 0; r < R_; r++) { sb1 += b1r[gk*R_ + r]; sb2 += b2r[gk*R_ + r]; }
        g_sumb1[k] = sb1; g_sumb2[k] = sb2;
        float fl = 0.f; int cnt = 0;
        for (int tt = 0; tt < T_; tt++) {
            int l = lc[gk*T_ + tt];
            fl += f_logdf(logdf, l);
            cnt += (l > 1);
        }
        g_flc[k] = fl; g_cnt[k] = cnt;
    }
}

// ---------------- Kernel B: per-candidate scoring ----------------
// grid = Z, block = 128
__global__ void kB(const int* __restrict__ indexes, const int* __restrict__ lc,
                   const float* __restrict__ lf, const float* __restrict__ log_pi,
                   const int* __restrict__ idx1a, const int* __restrict__ idx2a,
                   const float* __restrict__ br1, const float* __restrict__ br2,
                   const float* __restrict__ embJ, const float* __restrict__ logvp,
                   const float* __restrict__ Wq, const float* __restrict__ Wstat,
                   const float* __restrict__ logdf) {
    int z = blockIdx.x;
    int k = z / J_;
    int gk = indexes[k];
    int tid = threadIdx.x;
    __shared__ float slog[20];
    __shared__ float sQ[16], sP1[16], sP2[16], sstat[4];
    __shared__ float sred[128];

    int i1 = idx1a[z], i2 = idx2a[z];
    float b1 = br1[z], b2 = br2[z];
    const float* emb = embJ + (size_t)z*D_;

    if (tid < 20) {
        float sum = 0.f;
        if (tid < 16) {
            #pragma unroll 8
            for (int d = 0; d < D_; d++) sum += emb[d] * Wq[d*16 + tid];
        } else {
            int a = tid - 16;
            #pragma unroll 8
            for (int d = 0; d < D_; d++) sum += emb[d] * Wstat[d*A_ + a];
        }
        slog[tid] = sum;
    }
    __syncthreads();
    if (tid < 16) {
        int r = tid >> 2, c = tid & 3;
        float x = slog[tid];
        float sp = fmaxf(x, 0.f) + log1pf(__expf(-fabsf(x)));  // jax softplus = logaddexp(x,0)
        sQ[tid] = (r == c) ? 0.f : sp;
    }
    __syncthreads();
    if (tid < 4) {
        float rs = sQ[tid*4+0] + sQ[tid*4+1] + sQ[tid*4+2] + sQ[tid*4+3];
        sQ[tid*4 + tid] = -rs;
    }
    if (tid == 4) {
        float l0 = slog[16], l1 = slog[17], l2 = slog[18], l3 = slog[19];
        float m = fmaxf(fmaxf(l0,l1), fmaxf(l2,l3));
        float e0 = __expf(l0-m), e1 = __expf(l1-m), e2 = __expf(l2-m), e3 = __expf(l3-m);
        float inv = 1.f/(e0+e1+e2+e3);
        sstat[0]=e0*inv; sstat[1]=e1*inv; sstat[2]=e2*inv; sstat[3]=e3*inv;
    }
    __syncthreads();
    if (tid < 2) {
        float M[16], E[16];
        float bb = (tid == 0) ? b1 : b2;
        #pragma unroll
        for (int i = 0; i < 16; i++) M[i] = sQ[i] * bb;
        expm4(M, E);
        float* dst = (tid == 0) ? sP1 : sP2;
        #pragma unroll
        for (int i = 0; i < 16; i++) dst[i] = fmaxf(E[i], 1e-30f);  // clip like reference
    }
    __syncthreads();
    if (tid < 16) { g_P1[z*16 + tid] = sP1[tid]; g_P2[z*16 + tid] = sP2[tid]; }

    // New-node log-likelihood: sum_s log( sum_a (P1[a,:].e1)(P2[a,:].e2) stat[a] )
    const float4* r1 = (const float4*)(lf + (size_t)(gk*T_ + i1)*S_*A_);
    const float4* r2 = (const float4*)(lf + (size_t)(gk*T_ + i2)*S_*A_);
    float acc = 0.f;
    #pragma unroll
    for (int it = 0; it < 2; it++) {
        int s = tid + it*128;
        float4 v1 = r1[s], v2 = r2[s];
        float e10=__expf(v1.x), e11=__expf(v1.y), e12=__expf(v1.z), e13=__expf(v1.w);
        float e20=__expf(v2.x), e21=__expf(v2.y), e22=__expf(v2.z), e23=__expf(v2.w);
        float tot = 0.f;
        #pragma unroll
        for (int a = 0; a < 4; a++) {
            float m1 = sP1[a*4+0]*e10 + sP1[a*4+1]*e11 + sP1[a*4+2]*e12 + sP1[a*4+3]*e13;
            float m2 = sP2[a*4+0]*e20 + sP2[a*4+1]*e21 + sP2[a*4+2]*e22 + sP2[a*4+3]*e23;
            tot += m1 * m2 * sstat[a];
        }
        acc += __logf(tot);
    }
    sred[tid] = acc;
    __syncthreads();
    for (int off = 64; off > 0; off >>= 1) {
        if (tid < off) sred[tid] += sred[tid + off];
        __syncthreads();
    }
    if (tid == 0) {
        float ll_new = sred[0];
        float loglik = g_ctotal[k] - g_ckept[k*T_ + i1] - g_ckept[k*T_ + i2] + ll_new;
        float lbp = 2.f * (float)RP1 * LOG10F
                  - 10.f * (g_sumb1[k] + g_sumb2[k] + b1 + b2);
        int l1v = lc[gk*T_ + i1], l2v = lc[gk*T_ + i2];
        int nl = l1v + l2v;
        float flcnew = g_flc[k] - f_logdf(logdf, l1v) - f_logdf(logdf, l2v) + f_logdf(logdf, nl);
        float log_topo = -flcnew;
        int cnt = g_cnt[k] - (l1v > 1) - (l2v > 1) + 1;   // new_lc >= 2 always counts
        float lvm = __logf((float)cnt);
        float lpn = loglik + lbp + log_topo;
        float lw = lpn - log_pi[gk] + lvm - logvp[z];
        g_logw[z] = lw; g_lpn[z] = lpn; g_llik[z] = loglik;
    }
}

// ---------------- Kernel C: per-particle reduce over J ----------------
// grid = 1, block = 128
__global__ void kC(const float* __restrict__ gumbel, float* __restrict__ out) {
    int k = threadIdx.x;
    float w[J_];
    #pragma unroll
    for (int j = 0; j < J_; j++) w[j] = g_logw[k*J_ + j];
    float m = fmaxf(fmaxf(w[0], w[1]), fmaxf(w[2], w[3]));
    float se = __expf(w[0]-m) + __expf(w[1]-m) + __expf(w[2]-m) + __expf(w[3]-m);
    out[O10 + k] = m + __logf(se) - logf(4.0f);
    int best = 0;
    float bv = w[0] + gumbel[k*J_ + 0];
    #pragma unroll
    for (int j = 1; j < J_; j++) {
        float sv = w[j] + gumbel[k*J_ + j];
        if (sv > bv) { bv = sv; best = j; }   // first-max on ties, like jnp.argmax
    }
    g_sel[k] = best;
    int zs = k*J_ + best;
    out[O9 + k]  = g_lpn[zs];
    out[O11 + k] = g_llik[zs];
}

// ---------------- Kernel D: node-wise outputs (lc, h, embt, lf) ----------------
// grid = (31, K), block = 256
__global__ void kD(const int* __restrict__ indexes,
                   const int* __restrict__ idx1a, const int* __restrict__ idx2a,
                   const int* __restrict__ lc, const int* __restrict__ hashes,
                   const float* __restrict__ embt, const float* __restrict__ lf,
                   const float* __restrict__ embJ, float* __restrict__ out) {
    int i = blockIdx.x;         // node index 0..30
    int k = blockIdx.y;
    int tid = threadIdx.x;
    int zs = k*J_ + g_sel[k];
    int gk = indexes[k];
    int i1 = idx1a[zs], i2 = idx2a[zs];
    int a = min(i1, i2), b = max(i1, i2);

    float* olf = out + O8 + (size_t)(k*TM1 + i)*S_*A_;
    float* oet = out + O7 + (size_t)(k*TM1 + i)*D_;

    if (i < T_-2) {
        int t = i;
        if (t >= a) t++;
        if (t >= b) t++;
        const float4* src = (const float4*)(lf + (size_t)(gk*T_ + t)*S_*A_);
        ((float4*)olf)[tid] = src[tid];                 // 256 * float4 = 1024 floats
        if (tid < D_) oet[tid] = embt[(size_t)(gk*T_ + t)*D_ + tid];
        if (tid == 0) {
            out[O5 + k*TM1 + i] = (float)lc[gk*T_ + t];
            out[O6 + k*TM1 + i] = (float)hashes[gk*T_ + t];
        }
    } else {
        __shared__ float sP1[16], sP2[16];
        if (tid < 16) { sP1[tid] = g_P1[zs*16 + tid]; sP2[tid] = g_P2[zs*16 + tid]; }
        __syncthreads();
        const float4* r1 = (const float4*)(lf + (size_t)(gk*T_ + i1)*S_*A_);
        const float4* r2 = (const float4*)(lf + (size_t)(gk*T_ + i2)*S_*A_);
        float4 v1 = r1[tid], v2 = r2[tid];
        float e10=__expf(v1.x), e11=__expf(v1.y), e12=__expf(v1.z), e13=__expf(v1.w);
        float e20=__expf(v2.x), e21=__expf(v2.y), e22=__expf(v2.z), e23=__expf(v2.w);
        float4 res;
        float* rp = (float*)&res;
        #pragma unroll
        for (int aa = 0; aa < 4; aa++) {
            float m1 = sP1[aa*4+0]*e10 + sP1[aa*4+1]*e11 + sP1[aa*4+2]*e12 + sP1[aa*4+3]*e13;
            float m2 = sP2[aa*4+0]*e20 + sP2[aa*4+1]*e21 + sP2[aa*4+2]*e22 + sP2[aa*4+3]*e23;
            rp[aa] = __logf(m1) + __logf(m2);
        }
        ((float4*)olf)[tid] = res;
        if (tid < D_) oet[tid] = embJ[(size_t)zs*D_ + tid];
        if (tid == 0) {
            int l1 = lc[gk*T_ + i1], l2 = lc[gk*T_ + i2];
            out[O5 + k*TM1 + i] = (float)(l1 + l2);
            int h1 = hashes[gk*T_ + i1], h2 = hashes[gk*T_ + i2];
            int mn = min(h1, h2), mx = max(h1, h2);
            unsigned int hh = ((unsigned int)mn * 1000003u + (unsigned int)mx) * 40503u + 2531011u;
            out[O6 + k*TM1 + i] = (float)(int)hh;      // int32 wraparound, then cast
        }
    }
}

// ---------------- Kernel E: merge-history outputs ----------------
// grid = K, block = 256
__global__ void kE(const int* __restrict__ indexes,
                   const int* __restrict__ m1r, const int* __restrict__ m2r,
                   const float* __restrict__ b1r, const float* __restrict__ b2r,
                   const float* __restrict__ embr,
                   const int* __restrict__ idx1a, const int* __restrict__ idx2a,
                   const float* __restrict__ br1, const float* __restrict__ br2,
                   const float* __restrict__ embJ, float* __restrict__ out) {
    int k = blockIdx.x;
    int tid = threadIdx.x;
    int zs = k*J_ + g_sel[k];
    int gk = indexes[k];
    if (tid < RP1) {
        int r = tid;
        float v1, v2, vb1, vb2;
        if (r < R_) {
            v1 = (float)m1r[gk*R_ + r];
            v2 = (float)m2r[gk*R_ + r];
            vb1 = b1r[gk*R_ + r];
            vb2 = b2r[gk*R_ + r];
        } else {
            v1 = (float)idx1a[zs];
            v2 = (float)idx2a[zs];
            vb1 = br1[zs];
            vb2 = br2[zs];
        }
        out[O0 + k*RP1 + r] = v1;
        out[O1 + k*RP1 + r] = v2;
        out[O2 + k*RP1 + r] = vb1;
        out[O3 + k*RP1 + r] = vb2;
    }
    for (int idx = tid; idx < RP1*D_; idx += 256) {
        int r = idx / D_, d = idx % D_;
        float v = (r < R_) ? embr[(size_t)(gk*R_ + r)*D_ + d]
                           : embJ[(size_t)zs*D_ + d];
        out[O4 + (size_t)(k*RP1 + r)*D_ + d] = v;
    }
}

// ---------------- launch ----------------
extern "C" void kernel_launch(void* const* d_in, const int* in_sizes, int n_in,
                              void* d_out, int out_size) {
    const int*   indexes = (const int*)  d_in[0];
    const int*   m1r     = (const int*)  d_in[1];
    const int*   m2r     = (const int*)  d_in[2];
    const float* b1r     = (const float*)d_in[3];
    const float* b2r     = (const float*)d_in[4];
    const float* embr    = (const float*)d_in[5];
    const int*   lc      = (const int*)  d_in[6];
    const int*   hashes  = (const int*)  d_in[7];
    const float* embt    = (const float*)d_in[8];
    const float* lf      = (const float*)d_in[9];
    const float* log_pi  = (const float*)d_in[10];
    const int*   idx1a   = (const int*)  d_in[11];
    const int*   idx2a   = (const int*)  d_in[12];
    const float* br1     = (const float*)d_in[13];
    const float* br2     = (const float*)d_in[14];
    const float* embJ    = (const float*)d_in[15];
    const float* logvp   = (const float*)d_in[16];
    const float* gumbel  = (const float*)d_in[17];
    const float* Wq      = (const float*)d_in[18];
    const float* Wstat   = (const float*)d_in[19];
    const float* logdf   = (const float*)d_in[20];
    float* out = (float*)d_out;

    kA<<<K_, 256>>>(indexes, b1r, b2r, lc, embt, lf, Wstat, logdf);
    kB<<<Z_, 128>>>(indexes, lc, lf, log_pi, idx1a, idx2a, br1, br2,
                    embJ, logvp, Wq, Wstat, logdf);
    kC<<<1, K_>>>(gumbel, out);
    kD<<<dim3(TM1, K_), 256>>>(indexes, idx1a, idx2a, lc, hashes, embt, lf, embJ, out);
    kE<<<K_, 256>>>(indexes, m1r, m2r, b1r, b2r, embr, idx1a, idx2a, br1, br2, embJ, out);
}

// round 2
// speedup vs baseline: 1.3524x; 1.3524x over previous
#include <cuda_runtime.h>
#include <cuda_bf16.h>
#include <math.h>

// Problem constants
#define K_ 128
#define J_ 4
#define N_ 64
#define R_ 32
#define T_ 32
#define S_ 256
#define A_ 4
#define D_ 64
#define Z_ (K_*J_)   // 512
#define TM1 (T_-1)   // 31 nodes after merge
#define RP1 (R_+1)   // 33

// Output segment offsets (floats)
#define O0 0u
#define O1 4224u
#define O2 8448u
#define O3 12672u
#define O4 16896u
#define O5 287232u
#define O6 291200u
#define O7 295168u
#define O8 549120u
#define O9 4612352u
#define O10 4612480u
#define O11 4612608u

#define LOG10F 2.302585092994045684f
#define LOG4F  1.3862943611198906f

// ---------------- scratch ----------------
__device__ float g_ckept[K_*T_];
__device__ float g_ctotal[K_];
__device__ float g_sumb1[K_];
__device__ float g_sumb2[K_];
__device__ float g_flc[K_];
__device__ int   g_cnt[K_];
__device__ float g_llnew[Z_];
__device__ float g_P1[Z_*16];
__device__ float g_P2[Z_*16];

// ---------------- helpers ----------------
__device__ __forceinline__ float f_logdf(const float* logdf, int l) {
    int di = 2*l - 3;
    di = max(0, min(2*N_ - 1, di));
    return logdf[di];
}

// 4x4 matrix exponential: scaling-and-squaring + Taylor order 12.
__device__ void expm4(const float* M, float* E) {
    float nrm = 0.f;
    #pragma unroll
    for (int r = 0; r < 4; r++) {
        float rs = fabsf(M[r*4+0]) + fabsf(M[r*4+1]) + fabsf(M[r*4+2]) + fabsf(M[r*4+3]);
        nrm = fmaxf(nrm, rs);
    }
    int s = 0;
    while (nrm > 0.5f && s < 40) { nrm *= 0.5f; s++; }
    float sc = ldexpf(1.0f, -s);
    float A[16], Tm[16];
    #pragma unroll
    for (int i = 0; i < 16; i++) { A[i] = M[i] * sc; Tm[i] = A[i]; E[i] = A[i]; }
    E[0] += 1.f; E[5] += 1.f; E[10] += 1.f; E[15] += 1.f;
    for (int n = 2; n <= 12; n++) {
        float Tn[16];
        float invn = 1.0f / (float)n;
        #pragma unroll
        for (int r = 0; r < 4; r++)
            #pragma unroll
            for (int c = 0; c < 4; c++) {
                float sum = Tm[r*4+0]*A[0*4+c] + Tm[r*4+1]*A[1*4+c]
                          + Tm[r*4+2]*A[2*4+c] + Tm[r*4+3]*A[3*4+c];
                Tn[r*4+c] = sum * invn;
            }
        #pragma unroll
        for (int i = 0; i < 16; i++) { Tm[i] = Tn[i]; E[i] += Tn[i]; }
    }
    for (int q = 0; q < s; q++) {
        float Sq[16];
        #pragma unroll
        for (int r = 0; r < 4; r++)
            #pragma unroll
            for (int c = 0; c < 4; c++)
                Sq[r*4+c] = E[r*4+0]*E[0*4+c] + E[r*4+1]*E[1*4+c]
                          + E[r*4+2]*E[2*4+c] + E[r*4+3]*E[3*4+c];
        #pragma unroll
        for (int i = 0; i < 16; i++) E[i] = Sq[i];
    }
}

// ---------------- Kernel 1: fused per-particle constants (kA) + per-candidate
// expm & new-node site sums (kB compute). blocks [0,K): kA. [K,K+Z): kB. ----
__global__ void __launch_bounds__(256) k1(
        const int* __restrict__ indexes,
        const float* __restrict__ b1r, const float* __restrict__ b2r,
        const int* __restrict__ lc, const float* __restrict__ embt,
        const float* __restrict__ lf, const float* __restrict__ Wstat,
        const float* __restrict__ logdf,
        const int* __restrict__ idx1a, const int* __restrict__ idx2a,
        const float* __restrict__ br1, const float* __restrict__ br2,
        const float* __restrict__ embJ, const float* __restrict__ Wq) {
    int tid = threadIdx.x;
    if (blockIdx.x < K_) {
        // ----- kA: per-particle kept-node constants -----
        int k = blockIdx.x;
        int gk = indexes[k];
        __shared__ float s_logit[T_][A_];
        __shared__ float s_p[T_][A_];
        __shared__ float s_part[T_][8];
        __shared__ float s_c[T_];

        if (tid < T_*A_) {
            int t = tid >> 2, a = tid & 3;
            const float* e = embt + (size_t)(gk*T_ + t)*D_;
            float sum = 0.f;
            #pragma unroll 8
            for (int d = 0; d < D_; d++) sum += e[d] * Wstat[d*A_ + a];
            s_logit[t][a] = sum;
        }
        __syncthreads();
        if (tid < T_) {
            float l0 = s_logit[tid][0], l1 = s_logit[tid][1], l2 = s_logit[tid][2], l3 = s_logit[tid][3];
            float m = fmaxf(fmaxf(l0,l1), fmaxf(l2,l3));
            float e0 = __expf(l0-m), e1 = __expf(l1-m), e2 = __expf(l2-m), e3 = __expf(l3-m);
            float inv = 1.f/(e0+e1+e2+e3);
            s_p[tid][0]=e0*inv; s_p[tid][1]=e1*inv; s_p[tid][2]=e2*inv; s_p[tid][3]=e3*inv;
        }
        __syncthreads();
        {
            int t = tid >> 3, lane = tid & 7;
            float p0 = s_p[t][0], p1 = s_p[t][1], p2 = s_p[t][2], p3 = s_p[t][3];
            const float4* row = (const float4*)(lf + (size_t)(gk*T_ + t)*S_*A_);
            float acc = 0.f;
            #pragma unroll 4
            for (int i = 0; i < S_/8; i++) {
                float4 v = row[lane + 8*i];
                float dot = p0*__expf(v.x) + p1*__expf(v.y) + p2*__expf(v.z) + p3*__expf(v.w);
                acc += __logf(dot);
            }
            s_part[t][lane] = acc;
        }
        __syncthreads();
        if (tid < T_) {
            float c = 0.f;
            #pragma unroll
            for (int i = 0; i < 8; i++) c += s_part[tid][i];
            g_ckept[k*T_ + tid] = c;
            s_c[tid] = c;
        }
        __syncthreads();
        if (tid == 0) {
            float tot = 0.f;
            for (int i = 0; i < T_; i++) tot += s_c[i];
            g_ctotal[k] = tot;
            float sb1 = 0.f, sb2 = 0.f;
            for (int r = 0; r < R_; r++) { sb1 += b1r[gk*R_ + r]; sb2 += b2r[gk*R_ + r]; }
            g_sumb1[k] = sb1; g_sumb2[k] = sb2;
            float fl = 0.f; int cnt = 0;
            for (int tt = 0; tt < T_; tt++) {
                int l = lc[gk*T_ + tt];
                fl += f_logdf(logdf, l);
                cnt += (l > 1);
            }
            g_flc[k] = fl; g_cnt[k] = cnt;
        }
    } else {
        // ----- kB compute: expm + new-node site log-sum (no kA dependency) -----
        int z = blockIdx.x - K_;
        int k = z / J_;
        int gk = indexes[k];
        __shared__ float slog[20];
        __shared__ float sQ[16], sP1[16], sP2[16], sstat[4];
        __shared__ float sred[256];

        int i1 = idx1a[z], i2 = idx2a[z];
        float b1 = br1[z], b2 = br2[z];
        const float* emb = embJ + (size_t)z*D_;

        if (tid < 20) {
            float sum = 0.f;
            if (tid < 16) {
                #pragma unroll 8
                for (int d = 0; d < D_; d++) sum += emb[d] * Wq[d*16 + tid];
            } else {
                int a = tid - 16;
                #pragma unroll 8
                for (int d = 0; d < D_; d++) sum += emb[d] * Wstat[d*A_ + a];
            }
            slog[tid] = sum;
        }
        __syncthreads();
        if (tid < 16) {
            int r = tid >> 2, c = tid & 3;
            float x = slog[tid];
            float sp = fmaxf(x, 0.f) + log1pf(__expf(-fabsf(x)));
            sQ[tid] = (r == c) ? 0.f : sp;
        }
        __syncthreads();
        if (tid < 4) {
            float rs = sQ[tid*4+0] + sQ[tid*4+1] + sQ[tid*4+2] + sQ[tid*4+3];
            sQ[tid*4 + tid] = -rs;
        }
        if (tid == 4) {
            float l0 = slog[16], l1 = slog[17], l2 = slog[18], l3 = slog[19];
            float m = fmaxf(fmaxf(l0,l1), fmaxf(l2,l3));
            float e0 = __expf(l0-m), e1 = __expf(l1-m), e2 = __expf(l2-m), e3 = __expf(l3-m);
            float inv = 1.f/(e0+e1+e2+e3);
            sstat[0]=e0*inv; sstat[1]=e1*inv; sstat[2]=e2*inv; sstat[3]=e3*inv;
        }
        __syncthreads();
        if (tid < 2) {
            float M[16], E[16];
            float bb = (tid == 0) ? b1 : b2;
            #pragma unroll
            for (int i = 0; i < 16; i++) M[i] = sQ[i] * bb;
            expm4(M, E);
            float* dst = (tid == 0) ? sP1 : sP2;
            #pragma unroll
            for (int i = 0; i < 16; i++) dst[i] = fmaxf(E[i], 1e-30f);
        }
        __syncthreads();
        if (tid < 16) { g_P1[z*16 + tid] = sP1[tid]; g_P2[z*16 + tid] = sP2[tid]; }

        const float4* r1 = (const float4*)(lf + (size_t)(gk*T_ + i1)*S_*A_);
        const float4* r2 = (const float4*)(lf + (size_t)(gk*T_ + i2)*S_*A_);
        float4 v1 = r1[tid], v2 = r2[tid];
        float e10=__expf(v1.x), e11=__expf(v1.y), e12=__expf(v1.z), e13=__expf(v1.w);
        float e20=__expf(v2.x), e21=__expf(v2.y), e22=__expf(v2.z), e23=__expf(v2.w);
        float tot = 0.f;
        #pragma unroll
        for (int a = 0; a < 4; a++) {
            float m1 = sP1[a*4+0]*e10 + sP1[a*4+1]*e11 + sP1[a*4+2]*e12 + sP1[a*4+3]*e13;
            float m2 = sP2[a*4+0]*e20 + sP2[a*4+1]*e21 + sP2[a*4+2]*e22 + sP2[a*4+3]*e23;
            tot += m1 * m2 * sstat[a];
        }
        sred[tid] = __logf(tot);
        __syncthreads();
        for (int off = 128; off > 0; off >>= 1) {
            if (tid < off) sred[tid] += sred[tid + off];
            __syncthreads();
        }
        if (tid == 0) g_llnew[z] = sred[0];
    }
}

// ---------------- Kernel 2: selection (recomputed per block) + all outputs ----
// grid = (17, K), block = 256
//  i in [0,15): copy 2 kept nodes each (nodes 2i, 2i+1)
//  i == 15    : new-node lf/embt/lc/h
//  i == 16    : merge-history outputs + scalar outputs
__global__ void __launch_bounds__(256) k2(
        const int* __restrict__ indexes,
        const int* __restrict__ idx1a, const int* __restrict__ idx2a,
        const int* __restrict__ lc, const int* __restrict__ hashes,
        const float* __restrict__ embt, const float* __restrict__ lf,
        const float* __restrict__ embJ,
        const float* __restrict__ br1, const float* __restrict__ br2,
        const float* __restrict__ log_pi, const float* __restrict__ logvp,
        const float* __restrict__ gumbel, const float* __restrict__ logdf,
        const int* __restrict__ m1r, const int* __restrict__ m2r,
        const float* __restrict__ b1r, const float* __restrict__ b2r,
        const float* __restrict__ embr,
        float* __restrict__ out) {
    int i = blockIdx.x;
    int k = blockIdx.y;
    int tid = threadIdx.x;
    int gk = indexes[k];

    __shared__ float s_lw[4], s_lpn[4], s_llik[4], s_gum[4];
    __shared__ int s_sel;

    if (tid < 4) {
        int z = k*J_ + tid;
        int i1 = idx1a[z], i2 = idx2a[z];
        float loglik = g_ctotal[k] - g_ckept[k*T_ + i1] - g_ckept[k*T_ + i2] + g_llnew[z];
        float lbp = 2.f * (float)RP1 * LOG10F
                  - 10.f * (g_sumb1[k] + g_sumb2[k] + br1[z] + br2[z]);
        int l1v = lc[gk*T_ + i1], l2v = lc[gk*T_ + i2];
        float flcnew = g_flc[k] - f_logdf(logdf, l1v) - f_logdf(logdf, l2v)
                     + f_logdf(logdf, l1v + l2v);
        int cnt = g_cnt[k] - (l1v > 1) - (l2v > 1) + 1;
        float lpn = loglik + lbp - flcnew;
        float lw = lpn - log_pi[gk] + __logf((float)cnt) - logvp[z];
        s_lw[tid] = lw; s_lpn[tid] = lpn; s_llik[tid] = loglik;
        s_gum[tid] = lw + gumbel[z];
    }
    __syncthreads();
    if (tid == 0) {
        int best = 0; float bv = s_gum[0];
        #pragma unroll
        for (int j = 1; j < J_; j++) if (s_gum[j] > bv) { bv = s_gum[j]; best = j; }
        s_sel = best;
    }
    __syncthreads();
    int sel = s_sel;
    int zs = k*J_ + sel;
    int i1 = idx1a[zs], i2 = idx2a[zs];
    int a = min(i1, i2), b = max(i1, i2);

    if (i < 15) {
        // copy two kept nodes: n0 = 2i, n1 = 2i+1 (< 30)
        int n0 = 2*i, n1 = 2*i + 1;
        int t0 = n0; if (t0 >= a) t0++; if (t0 >= b) t0++;
        int t1 = n1; if (t1 >= a) t1++; if (t1 >= b) t1++;
        const float4* src0 = (const float4*)(lf + (size_t)(gk*T_ + t0)*S_*A_);
        const float4* src1 = (const float4*)(lf + (size_t)(gk*T_ + t1)*S_*A_);
        float4* d0 = (float4*)(out + O8 + (size_t)(k*TM1 + n0)*S_*A_);
        float4* d1 = (float4*)(out + O8 + (size_t)(k*TM1 + n1)*S_*A_);
        float4 v0 = src0[tid];
        float4 v1 = src1[tid];
        __stcs(&d0[tid], v0);
        __stcs(&d1[tid], v1);
        if (tid < D_) {
            out[O7 + (size_t)(k*TM1 + n0)*D_ + tid] = embt[(size_t)(gk*T_ + t0)*D_ + tid];
        } else if (tid < 2*D_) {
            int d = tid - D_;
            out[O7 + (size_t)(k*TM1 + n1)*D_ + d] = embt[(size_t)(gk*T_ + t1)*D_ + d];
        }
        if (tid == 0) {
            out[O5 + k*TM1 + n0] = (float)lc[gk*T_ + t0];
            out[O6 + k*TM1 + n0] = (float)hashes[gk*T_ + t0];
            out[O5 + k*TM1 + n1] = (float)lc[gk*T_ + t1];
            out[O6 + k*TM1 + n1] = (float)hashes[gk*T_ + t1];
        }
    } else if (i == 15) {
        // new node at position 30
        __shared__ float sP1[16], sP2[16];
        if (tid < 16) { sP1[tid] = g_P1[zs*16 + tid]; sP2[tid] = g_P2[zs*16 + tid]; }
        __syncthreads();
        const float4* r1 = (const float4*)(lf + (size_t)(gk*T_ + i1)*S_*A_);
        const float4* r2 = (const float4*)(lf + (size_t)(gk*T_ + i2)*S_*A_);
        float4 v1 = r1[tid], v2 = r2[tid];
        float e10=__expf(v1.x), e11=__expf(v1.y), e12=__expf(v1.z), e13=__expf(v1.w);
        float e20=__expf(v2.x), e21=__expf(v2.y), e22=__expf(v2.z), e23=__expf(v2.w);
        float4 res;
        float* rp = (float*)&res;
        #pragma unroll
        for (int aa = 0; aa < 4; aa++) {
            float m1 = sP1[aa*4+0]*e10 + sP1[aa*4+1]*e11 + sP1[aa*4+2]*e12 + sP1[aa*4+3]*e13;
            float m2 = sP2[aa*4+0]*e20 + sP2[aa*4+1]*e21 + sP2[aa*4+2]*e22 + sP2[aa*4+3]*e23;
            rp[aa] = __logf(m1) + __logf(m2);
        }
        float4* dlf = (float4*)(out + O8 + (size_t)(k*TM1 + 30)*S_*A_);
        __stcs(&dlf[tid], res);
        if (tid < D_) out[O7 + (size_t)(k*TM1 + 30)*D_ + tid] = embJ[(size_t)zs*D_ + tid];
        if (tid == 0) {
            int l1 = lc[gk*T_ + i1], l2 = lc[gk*T_ + i2];
            out[O5 + k*TM1 + 30] = (float)(l1 + l2);
            int h1 = hashes[gk*T_ + i1], h2 = hashes[gk*T_ + i2];
            int mn = min(h1, h2), mx = max(h1, h2);
            unsigned int hh = ((unsigned int)mn * 1000003u + (unsigned int)mx) * 40503u + 2531011u;
            out[O6 + k*TM1 + 30] = (float)(int)hh;
        }
    } else {
        // merge-history + scalar outputs
        if (tid < RP1) {
            int r = tid;
            float v1, v2, vb1, vb2;
            if (r < R_) {
                v1 = (float)m1r[gk*R_ + r];
                v2 = (float)m2r[gk*R_ + r];
                vb1 = b1r[gk*R_ + r];
                vb2 = b2r[gk*R_ + r];
            } else {
                v1 = (float)i1;
                v2 = (float)i2;
                vb1 = br1[zs];
                vb2 = br2[zs];
            }
            out[O0 + k*RP1 + r] = v1;
            out[O1 + k*RP1 + r] = v2;
            out[O2 + k*RP1 + r] = vb1;
            out[O3 + k*RP1 + r] = vb2;
        }
        for (int idx = tid; idx < RP1*D_; idx += 256) {
            int r = idx / D_, d = idx % D_;
            float v = (r < R_) ? embr[(size_t)(gk*R_ + r)*D_ + d]
                               : embJ[(size_t)zs*D_ + d];
            out[O4 + (size_t)(k*RP1 + r)*D_ + d] = v;
        }
        if (tid == 0) {
            float m = fmaxf(fmaxf(s_lw[0], s_lw[1]), fmaxf(s_lw[2], s_lw[3]));
            float se = __expf(s_lw[0]-m) + __expf(s_lw[1]-m)
                     + __expf(s_lw[2]-m) + __expf(s_lw[3]-m);
            out[O10 + k] = m + __logf(se) - LOG4F;
            out[O9 + k]  = s_lpn[sel];
            out[O11 + k] = s_llik[sel];
        }
    }
}

// ---------------- launch ----------------
extern "C" void kernel_launch(void* const* d_in, const int* in_sizes, int n_in,
                              void* d_out, int out_size) {
    const int*   indexes = (const int*)  d_in[0];
    const int*   m1r     = (const int*)  d_in[1];
    const int*   m2r     = (const int*)  d_in[2];
    const float* b1r     = (const float*)d_in[3];
    const float* b2r     = (const float*)d_in[4];
    const float* embr    = (const float*)d_in[5];
    const int*   lc      = (const int*)  d_in[6];
    const int*   hashes  = (const int*)  d_in[7];
    const float* embt    = (const float*)d_in[8];
    const float* lf      = (const float*)d_in[9];
    const float* log_pi  = (const float*)d_in[10];
    const int*   idx1a   = (const int*)  d_in[11];
    const int*   idx2a   = (const int*)  d_in[12];
    const float* br1     = (const float*)d_in[13];
    const float* br2     = (const float*)d_in[14];
    const float* embJ    = (const float*)d_in[15];
    const float* logvp   = (const float*)d_in[16];
    const float* gumbel  = (const float*)d_in[17];
    const float* Wq      = (const float*)d_in[18];
    const float* Wstat   = (const float*)d_in[19];
    const float* logdf   = (const float*)d_in[20];
    float* out = (float*)d_out;

    k1<<<K_ + Z_, 256>>>(indexes, b1r, b2r, lc, embt, lf, Wstat, logdf,
                         idx1a, idx2a, br1, br2, embJ, Wq);
    k2<<<dim3(17, K_), 256>>>(indexes, idx1a, idx2a, lc, hashes, embt, lf, embJ,
                              br1, br2, log_pi, logvp, gumbel, logdf,
                              m1r, m2r, b1r, b2r, embr, out);
}